// round 14
// baseline (speedup 1.0000x reference)
#include <cuda_runtime.h>
#include <cuda_fp16.h>
#include <math_constants.h>

// ---------------- problem constants ----------------
#define BATCH   32
#define Q_LEN   32
#define HID     128
#define DOC_LEN 128
#define K_CAND  256
#define K_OUT   16
#define N_PIDS  20000
#define N_EMB   (N_PIDS * DOC_LEN)

// fp16 chunk tile pitch: 40 halves (80 B) -> 20-bank row stride: 8 consecutive
// rows cover all 32 banks => conflict-free ldmatrix AND STS.64.
#define HPITCH_U32 20            // pitch in u32 (40 halves)

typedef unsigned long long u64;
typedef unsigned int u32;

// ---------------- device scratch ----------------
__device__ int    g_upids[BATCH * K_CAND];
__device__ int    g_ucnt[BATCH];
__device__ float  g_scores[BATCH * K_CAND];
// q pre-split fp16 B fragments: [b][s=8][t=4][lane=32] -> uint2 (b0,b1), hi & lo
__device__ uint2  g_qfh[BATCH * 8 * 4 * 32];
__device__ uint2  g_qfl[BATCH * 8 * 4 * 32];
__device__ int    g_done[BATCH];    // zero-init; reset by finisher each launch

// ---------------- helpers ----------------
__device__ __forceinline__ void split_h2(float2 v, u32& hi, u32& lo) {
    __half2 h = __float22half2_rn(v);
    float2 hf = __half22float2(h);
    __half2 l = __float22half2_rn(make_float2(v.x - hf.x, v.y - hf.y));
    hi = *reinterpret_cast<u32*>(&h);
    lo = *reinterpret_cast<u32*>(&l);
}
__device__ __forceinline__ void mma16(float* c, const u32* a, const u32* b) {
    asm volatile(
        "mma.sync.aligned.m16n8k16.row.col.f32.f16.f16.f32 "
        "{%0,%1,%2,%3}, {%4,%5,%6,%7}, {%8,%9}, {%0,%1,%2,%3};"
        : "+f"(c[0]), "+f"(c[1]), "+f"(c[2]), "+f"(c[3])
        : "r"(a[0]), "r"(a[1]), "r"(a[2]), "r"(a[3]), "r"(b[0]), "r"(b[1]));
}
__device__ __forceinline__ void ldmx4(u32* r, u32 addr) {
    asm volatile(
        "ldmatrix.sync.aligned.m8n8.x4.shared.b16 {%0,%1,%2,%3}, [%4];"
        : "=r"(r[0]), "=r"(r[1]), "=r"(r[2]), "=r"(r[3]) : "r"(addr));
}
// monotone map: ascending u32 <=> ascending float (works for -inf)
__device__ __forceinline__ u32 fmap(float f) {
    u32 s = __float_as_uint(f);
    return (s & 0x80000000u) ? ~s : (s | 0x80000000u);
}

// ---------------- kernel 1: prep (dedup for bid<32, qprep for bid>=32) -----
__global__ void prep_kernel(const void* idx_raw, const float* __restrict__ qv) {
    const int role = blockIdx.x >> 5;
    const int b    = blockIdx.x & 31;
    const int t    = threadIdx.x;

    if (role == 1) {
        const float* src = qv + (size_t)b * Q_LEN * HID;
        uint2* dh = g_qfh + (size_t)b * (8 * 4 * 32);
        uint2* dl = g_qfl + (size_t)b * (8 * 4 * 32);
        for (int idx = t; idx < 8 * 4 * 32; idx += 256) {
            int s  = idx >> 7;
            int tt = (idx >> 5) & 3;
            int l  = idx & 31;
            int n  = 8 * tt + (l >> 2);
            int k0 = 16 * s + 2 * (l & 3);
            u32 b0h, b0l, b1h, b1l;
            split_h2(make_float2(src[n * HID + k0],     src[n * HID + k0 + 1]), b0h, b0l);
            split_h2(make_float2(src[n * HID + k0 + 8], src[n * HID + k0 + 9]), b1h, b1l);
            dh[idx] = make_uint2(b0h, b1h);
            dl[idx] = make_uint2(b0l, b1l);
        }
        return;
    }

    // ---- dedup: sorted unique pids ----
    __shared__ int pids[K_CAND];
    __shared__ int wsum[8];
    __shared__ int s_ok;

    if (t == 0) s_ok = 1;
    __syncthreads();
    if (t < 128) {
        long long v = ((const long long*)idx_raw)[b * 128 + t];
        if (v < 0 || v >= (long long)N_EMB) atomicAnd(&s_ok, 0);
    }
    __syncthreads();
    const int is64 = s_ok;

    long long v;
    if (is64) v = ((const long long*)idx_raw)[b * K_CAND + t];
    else      v = (long long)(((const int*)idx_raw)[b * K_CAND + t]);
    pids[t] = (int)(v >> 7);   // emb2pid[i] == i / 128
    __syncthreads();

    // bitonic sort: partner t^j is warp-local when j<32 -> syncwarp suffices
    for (int k = 2; k <= K_CAND; k <<= 1) {
        for (int j = k >> 1; j > 0; j >>= 1) {
            int ixj = t ^ j;
            if (ixj > t) {
                int a = pids[t], c = pids[ixj];
                bool up = ((t & k) == 0);
                if ((a > c) == up) { pids[t] = c; pids[ixj] = a; }
            }
            if (j >= 32) __syncthreads();
            else         __syncwarp();
        }
    }
    __syncthreads();

    int myv  = pids[t];
    int flag = (t == 0) || (myv != pids[t - 1]);
    unsigned mask = __ballot_sync(0xffffffffu, flag);
    int lane = t & 31, w = t >> 5;
    int pre  = __popc(mask & ((1u << lane) - 1));
    if (lane == 31) wsum[w] = pre + flag;
    __syncthreads();
    int base = 0;
    for (int i = 0; i < w; i++) base += wsum[i];
    int pos = base + pre;
    if (flag) g_upids[b * K_CAND + pos] = myv;
    if (t == K_CAND - 1) g_ucnt[b] = pos + flag;
}

// ---------------- kernel 2: 3xFP16 m16n8k16 scoring + fused top-16 ---------
// r13 mainloop byte-identical. Tail: per-batch done counter; the last CTA of
// each batch sorts all 256 scores in smem and writes the outputs.
__global__ void __launch_bounds__(128, 4)
score_kernel(const float* __restrict__ vectors,
             float* __restrict__ out, int out_size) {
    __shared__ u32 sHI[2][DOC_LEN * HPITCH_U32];   // 10 KB x2
    __shared__ u32 sLO[2][DOC_LEN * HPITCH_U32];   // 10 KB x2
    __shared__ float red[4 * 32];
    __shared__ int  s_last;
    __shared__ u64  keys[K_CAND];

    const int b    = blockIdx.x;
    const int slot = blockIdx.y;
    const int tid  = threadIdx.x;
    const int wid  = tid >> 5;
    const int lane = tid & 31;

    if (slot < g_ucnt[b]) {
        const int pid = g_upids[b * K_CAND + slot];
        const float* doc = vectors + (size_t)pid * DOC_LEN * HID;

        // staging pattern: 8 rows {16r + tid>>3}, fixed col4 = 4*(tid&7)
        const int srow0 = tid >> 3;
        const int scol4 = 4 * (tid & 7);

        float4 buf[8];
#pragma unroll
        for (int r = 0; r < 8; r++)
            buf[r] = __ldg((const float4*)(doc + (16 * r + srow0) * HID + scol4));

        const uint2* qfh = g_qfh + (size_t)b * (8 * 4 * 32) + lane;
        const uint2* qfl = g_qfl + (size_t)b * (8 * 4 * 32) + lane;
        const u32 hibase0 = (u32)__cvta_generic_to_shared(&sHI[0][0]);
        const u32 hibase1 = (u32)__cvta_generic_to_shared(&sHI[1][0]);
        const u32 lobase0 = (u32)__cvta_generic_to_shared(&sLO[0][0]);
        const u32 lobase1 = (u32)__cvta_generic_to_shared(&sLO[1][0]);

        float acc[2][4][4];
#pragma unroll
        for (int mt = 0; mt < 2; mt++)
#pragma unroll
            for (int t = 0; t < 4; t++)
#pragma unroll
                for (int r = 0; r < 4; r++) acc[mt][t][r] = 0.0f;

        const u32 lm_row = (u32)(lane & 15) * (HPITCH_U32 * 4);
        const u32 lm_col = (u32)(lane >> 4) * 16;

#pragma unroll
        for (int c = 0; c < 4; c++) {
            const int bsel = c & 1;
            const u32 hib = bsel ? hibase1 : hibase0;
            const u32 lob = bsel ? lobase1 : lobase0;
            u32* Hd = sHI[bsel];
            u32* Ld = sLO[bsel];

            // convert chunk c; issue chunk c+1's LDG as each value is consumed
#pragma unroll
            for (int r = 0; r < 8; r++) {
                float4 v = buf[r];
                if (c < 3)
                    buf[r] = __ldg((const float4*)(doc + (16 * r + srow0) * HID
                                                   + (c + 1) * 32 + scol4));
                u32 h0, l0, h1, l1;
                split_h2(make_float2(v.x, v.y), h0, l0);
                split_h2(make_float2(v.z, v.w), h1, l1);
                int u = (16 * r + srow0) * HPITCH_U32 + (scol4 >> 1);
                *(uint2*)(Hd + u) = make_uint2(h0, h1);
                *(uint2*)(Ld + u) = make_uint2(l0, l1);
            }
            __syncthreads();   // single barrier per chunk

#pragma unroll
            for (int si = 0; si < 2; si++) {
                const int s = 2 * c + si;           // k16 step 0..7
                uint2 qh[4], ql[4];
#pragma unroll
                for (int t = 0; t < 4; t++) {
                    qh[t] = __ldg(&qfh[(s * 4 + t) * 32]);
                    ql[t] = __ldg(&qfl[(s * 4 + t) * 32]);
                }
                u32 ahi[2][4], alo[2][4];
#pragma unroll
                for (int mt = 0; mt < 2; mt++) {
                    u32 off = (u32)((32 * wid + 16 * mt) * (HPITCH_U32 * 4))
                            + lm_row + 32 * si + lm_col;
                    ldmx4(ahi[mt], hib + off);
                    ldmx4(alo[mt], lob + off);
                }
#pragma unroll
                for (int t = 0; t < 4; t++) {
                    u32 bh[2] = { qh[t].x, qh[t].y };
                    u32 bl[2] = { ql[t].x, ql[t].y };
#pragma unroll
                    for (int mt = 0; mt < 2; mt++) {
                        mma16(acc[mt][t], ahi[mt], bh);   // hi*hi
                        mma16(acc[mt][t], ahi[mt], bl);   // hi*lo
                        mma16(acc[mt][t], alo[mt], bh);   // lo*hi
                    }
                }
            }
        }

        // epilogue: per-q max over this warp's 32 docs
#pragma unroll
        for (int t = 0; t < 4; t++) {
            float mx0 = fmaxf(acc[0][t][0], acc[0][t][2]);
            mx0 = fmaxf(mx0, fmaxf(acc[1][t][0], acc[1][t][2]));
            float mx1 = fmaxf(acc[0][t][1], acc[0][t][3]);
            mx1 = fmaxf(mx1, fmaxf(acc[1][t][1], acc[1][t][3]));
#pragma unroll
            for (int o = 4; o <= 16; o <<= 1) {
                mx0 = fmaxf(mx0, __shfl_xor_sync(0xffffffffu, mx0, o));
                mx1 = fmaxf(mx1, __shfl_xor_sync(0xffffffffu, mx1, o));
            }
            if (lane < 4) {
                red[wid * 32 + 8 * t + 2 * lane + 0] = mx0;
                red[wid * 32 + 8 * t + 2 * lane + 1] = mx1;
            }
        }
        __syncthreads();

        if (wid == 0) {
            float m = fmaxf(fmaxf(red[lane], red[32 + lane]),
                            fmaxf(red[64 + lane], red[96 + lane]));
#pragma unroll
            for (int o = 16; o > 0; o >>= 1)
                m += __shfl_xor_sync(0xffffffffu, m, o);
            if (lane == 0)
                g_scores[b * K_CAND + slot] = m * (1.0f / (float)Q_LEN);
        }
    } else {
        if (tid == 0) g_scores[b * K_CAND + slot] = -CUDART_INF_F;
    }

    // ---------------- fused top-16 tail (last-done CTA per batch) ----------
    __threadfence();
    if (tid == 0) {
        int old = atomicAdd(&g_done[b], 1);
        s_last = (old == K_CAND - 1);
    }
    __syncthreads();
    if (!s_last) return;

#pragma unroll
    for (int h = 0; h < 2; h++) {
        int i = 128 * h + tid;
        float sc = g_scores[b * K_CAND + i];
        keys[i] = ((u64)(~fmap(sc)) << 32) | (u32)i;
    }
    __syncthreads();
    for (int k = 2; k <= K_CAND; k <<= 1) {
        for (int j = k >> 1; j > 0; j >>= 1) {
#pragma unroll
            for (int h = 0; h < 2; h++) {
                int i = 128 * h + tid;
                int ixj = i ^ j;
                if (ixj > i) {
                    u64 a = keys[i], c = keys[ixj];
                    bool up = ((i & k) == 0);
                    if ((a > c) == up) { keys[i] = c; keys[ixj] = a; }
                }
            }
            __syncthreads();
        }
    }
    if (tid < K_OUT) {
        int slotw = (int)(keys[tid] & 0xffffffffu);
        out[b * K_OUT + tid] = (float)g_upids[b * K_CAND + slotw];
        if (out_size >= BATCH * K_OUT * 2)
            out[BATCH * K_OUT + b * K_OUT + tid] = g_scores[b * K_CAND + slotw];
    }
    if (tid == 0) g_done[b] = 0;    // restore for next graph replay
}

// ---------------- launcher ----------------
extern "C" void kernel_launch(void* const* d_in, const int* in_sizes, int n_in,
                              void* d_out, int out_size) {
    int qi = 0, ii = 1, vi = 3;
    for (int i = 0; i < n_in; i++) {
        if (in_sizes[i] == BATCH * Q_LEN * HID)            qi = i;
        else if (in_sizes[i] == BATCH * K_CAND)            ii = i;
        else if (in_sizes[i] == N_PIDS * DOC_LEN * HID)    vi = i;
    }
    const float* q       = (const float*)d_in[qi];
    const void*  idx     = d_in[ii];
    const float* vectors = (const float*)d_in[vi];

    prep_kernel<<<64, 256>>>(idx, q);

    dim3 grid(BATCH, K_CAND);
    score_kernel<<<grid, 128>>>(vectors, (float*)d_out, out_size);
}

// round 15
// speedup vs baseline: 1.1513x; 1.1513x over previous
#include <cuda_runtime.h>
#include <cuda_fp16.h>
#include <math_constants.h>

// ---------------- problem constants ----------------
#define BATCH   32
#define Q_LEN   32
#define HID     128
#define DOC_LEN 128
#define K_CAND  256
#define K_OUT   16
#define N_PIDS  20000
#define N_EMB   (N_PIDS * DOC_LEN)

typedef unsigned long long u64;
typedef unsigned int u32;

// ---------------- device scratch ----------------
__device__ int    g_upids[BATCH * K_CAND];
__device__ int    g_ucnt[BATCH];
__device__ float  g_scores[BATCH * K_CAND];
// q pre-split fp16 B fragments: [b][s=8][t=4][lane=32] -> uint2 (b0,b1), hi & lo
__device__ uint2  g_qfh[BATCH * 8 * 4 * 32];
__device__ uint2  g_qfl[BATCH * 8 * 4 * 32];

// ---------------- helpers ----------------
__device__ __forceinline__ void split_h2(float2 v, u32& hi, u32& lo) {
    __half2 h = __float22half2_rn(v);
    float2 hf = __half22float2(h);
    __half2 l = __float22half2_rn(make_float2(v.x - hf.x, v.y - hf.y));
    hi = *reinterpret_cast<u32*>(&h);
    lo = *reinterpret_cast<u32*>(&l);
}
__device__ __forceinline__ void mma16(float* c, const u32* a, const u32* b) {
    asm volatile(
        "mma.sync.aligned.m16n8k16.row.col.f32.f16.f16.f32 "
        "{%0,%1,%2,%3}, {%4,%5,%6,%7}, {%8,%9}, {%0,%1,%2,%3};"
        : "+f"(c[0]), "+f"(c[1]), "+f"(c[2]), "+f"(c[3])
        : "r"(a[0]), "r"(a[1]), "r"(a[2]), "r"(a[3]), "r"(b[0]), "r"(b[1]));
}
// monotone map: ascending u32 <=> ascending float (works for -inf)
__device__ __forceinline__ u32 fmap(float f) {
    u32 s = __float_as_uint(f);
    return (s & 0x80000000u) ? ~s : (s | 0x80000000u);
}

// ---------------- kernel 1: prep (dedup for bid<32, qprep for bid>=32) -----
__global__ void prep_kernel(const void* idx_raw, const float* __restrict__ qv) {
    const int role = blockIdx.x >> 5;
    const int b    = blockIdx.x & 31;
    const int t    = threadIdx.x;

    if (role == 1) {
        const float* src = qv + (size_t)b * Q_LEN * HID;
        uint2* dh = g_qfh + (size_t)b * (8 * 4 * 32);
        uint2* dl = g_qfl + (size_t)b * (8 * 4 * 32);
        for (int idx = t; idx < 8 * 4 * 32; idx += 256) {
            int s  = idx >> 7;
            int tt = (idx >> 5) & 3;
            int l  = idx & 31;
            int n  = 8 * tt + (l >> 2);
            int k0 = 16 * s + 2 * (l & 3);
            u32 b0h, b0l, b1h, b1l;
            split_h2(make_float2(src[n * HID + k0],     src[n * HID + k0 + 1]), b0h, b0l);
            split_h2(make_float2(src[n * HID + k0 + 8], src[n * HID + k0 + 9]), b1h, b1l);
            dh[idx] = make_uint2(b0h, b1h);
            dl[idx] = make_uint2(b0l, b1l);
        }
        return;
    }

    // ---- dedup: sorted unique pids ----
    __shared__ int pids[K_CAND];
    __shared__ int wsum[8];
    __shared__ int s_ok;

    if (t == 0) s_ok = 1;
    __syncthreads();
    if (t < 128) {
        long long v = ((const long long*)idx_raw)[b * 128 + t];
        if (v < 0 || v >= (long long)N_EMB) atomicAnd(&s_ok, 0);
    }
    __syncthreads();
    const int is64 = s_ok;

    long long v;
    if (is64) v = ((const long long*)idx_raw)[b * K_CAND + t];
    else      v = (long long)(((const int*)idx_raw)[b * K_CAND + t]);
    pids[t] = (int)(v >> 7);   // emb2pid[i] == i / 128
    __syncthreads();

    for (int k = 2; k <= K_CAND; k <<= 1) {
        for (int j = k >> 1; j > 0; j >>= 1) {
            int ixj = t ^ j;
            if (ixj > t) {
                int a = pids[t], c = pids[ixj];
                bool up = ((t & k) == 0);
                if ((a > c) == up) { pids[t] = c; pids[ixj] = a; }
            }
            if (j >= 32) __syncthreads();
            else         __syncwarp();
        }
    }
    __syncthreads();

    int myv  = pids[t];
    int flag = (t == 0) || (myv != pids[t - 1]);
    unsigned mask = __ballot_sync(0xffffffffu, flag);
    int lane = t & 31, w = t >> 5;
    int pre  = __popc(mask & ((1u << lane) - 1));
    if (lane == 31) wsum[w] = pre + flag;
    __syncthreads();
    int base = 0;
    for (int i = 0; i < w; i++) base += wsum[i];
    int pos = base + pre;
    if (flag) g_upids[b * K_CAND + pos] = myv;
    if (t == K_CAND - 1) g_ucnt[b] = pos + flag;
}

// ---------------- kernel 2: direct-LDG 3xFP16 m16n8k16 scoring -------------
// No doc smem staging: each lane LDG.64s exactly the float2 pairs its MMA
// A-fragment needs (byte-perfect 32B sectors), splits to fp16 hi/lo in regs.
// L1 traffic per tile: 72 KB (vs 136 KB with smem round-trip). No barriers
// in the mainloop; warps fully independent.
__global__ void __launch_bounds__(128, 4)
score_kernel(const float* __restrict__ vectors) {
    __shared__ float red[4 * 32];

    const int b    = blockIdx.x;
    const int slot = blockIdx.y;
    const int tid  = threadIdx.x;
    const int wid  = tid >> 5;
    const int lane = tid & 31;

    if (slot >= g_ucnt[b]) {
        if (tid == 0) g_scores[b * K_CAND + slot] = -CUDART_INF_F;
        return;
    }
    const int pid = g_upids[b * K_CAND + slot];
    const float* doc = vectors + (size_t)pid * DOC_LEN * HID;

    // per-lane fragment base: row group g = lane>>2, col pair c = lane&3
    const float* ap = doc + (size_t)(32 * wid + (lane >> 2)) * HID + 2 * (lane & 3);
    const uint2* qfh = g_qfh + (size_t)b * (8 * 4 * 32) + lane;
    const uint2* qfl = g_qfl + (size_t)b * (8 * 4 * 32) + lane;

    float acc[2][4][4];
#pragma unroll
    for (int mt = 0; mt < 2; mt++)
#pragma unroll
        for (int t = 0; t < 4; t++)
#pragma unroll
            for (int r = 0; r < 4; r++) acc[mt][t][r] = 0.0f;

    // fragment buffers: [buffer parity][mt][frag 0..3] float2
    float2 fr[2][2][4];

    // load step 0 fragments
#pragma unroll
    for (int mt = 0; mt < 2; mt++) {
        const float* p = ap + mt * 16 * HID;
        fr[0][mt][0] = __ldg((const float2*)(p));
        fr[0][mt][1] = __ldg((const float2*)(p + 8 * HID));
        fr[0][mt][2] = __ldg((const float2*)(p + 8));
        fr[0][mt][3] = __ldg((const float2*)(p + 8 * HID + 8));
    }

#pragma unroll
    for (int s = 0; s < 8; s++) {
        const int cur = s & 1;
        // prefetch step s+1 fragments
        if (s < 7) {
#pragma unroll
            for (int mt = 0; mt < 2; mt++) {
                const float* p = ap + mt * 16 * HID + 16 * (s + 1);
                fr[cur ^ 1][mt][0] = __ldg((const float2*)(p));
                fr[cur ^ 1][mt][1] = __ldg((const float2*)(p + 8 * HID));
                fr[cur ^ 1][mt][2] = __ldg((const float2*)(p + 8));
                fr[cur ^ 1][mt][3] = __ldg((const float2*)(p + 8 * HID + 8));
            }
        }
        // q fragments for this step
        uint2 qh[4], ql[4];
#pragma unroll
        for (int t = 0; t < 4; t++) {
            qh[t] = __ldg(&qfh[(s * 4 + t) * 32]);
            ql[t] = __ldg(&qfl[(s * 4 + t) * 32]);
        }
        // convert doc fragments to fp16 hi/lo
        u32 ahi[2][4], alo[2][4];
#pragma unroll
        for (int mt = 0; mt < 2; mt++)
#pragma unroll
            for (int r = 0; r < 4; r++)
                split_h2(fr[cur][mt][r], ahi[mt][r], alo[mt][r]);
        // 3-term MMA
#pragma unroll
        for (int t = 0; t < 4; t++) {
            u32 bh[2] = { qh[t].x, qh[t].y };
            u32 bl[2] = { ql[t].x, ql[t].y };
#pragma unroll
            for (int mt = 0; mt < 2; mt++) {
                mma16(acc[mt][t], ahi[mt], bh);   // hi*hi
                mma16(acc[mt][t], ahi[mt], bl);   // hi*lo
                mma16(acc[mt][t], alo[mt], bh);   // lo*hi
            }
        }
    }

    // epilogue: per-q max over this warp's 32 docs
    // C frag: c0(row g, col 2c), c1(+1), c2(row g+8, col 2c), c3(+1)
#pragma unroll
    for (int t = 0; t < 4; t++) {
        float mx0 = fmaxf(acc[0][t][0], acc[0][t][2]);
        mx0 = fmaxf(mx0, fmaxf(acc[1][t][0], acc[1][t][2]));
        float mx1 = fmaxf(acc[0][t][1], acc[0][t][3]);
        mx1 = fmaxf(mx1, fmaxf(acc[1][t][1], acc[1][t][3]));
#pragma unroll
        for (int o = 4; o <= 16; o <<= 1) {
            mx0 = fmaxf(mx0, __shfl_xor_sync(0xffffffffu, mx0, o));
            mx1 = fmaxf(mx1, __shfl_xor_sync(0xffffffffu, mx1, o));
        }
        if (lane < 4) {
            red[wid * 32 + 8 * t + 2 * lane + 0] = mx0;
            red[wid * 32 + 8 * t + 2 * lane + 1] = mx1;
        }
    }
    __syncthreads();

    if (wid == 0) {
        float m = fmaxf(fmaxf(red[lane], red[32 + lane]),
                        fmaxf(red[64 + lane], red[96 + lane]));
#pragma unroll
        for (int o = 16; o > 0; o >>= 1)
            m += __shfl_xor_sync(0xffffffffu, m, o);
        if (lane == 0)
            g_scores[b * K_CAND + slot] = m * (1.0f / (float)Q_LEN);
    }
}

// ---------------- kernel 3: bitonic-sort top-16 ----------------------------
__global__ void topk_kernel(float* __restrict__ out, int out_size) {
    const int b = blockIdx.x;
    const int t = threadIdx.x;    // 256
    __shared__ u64 keys[K_CAND];

    float sc = g_scores[b * K_CAND + t];
    keys[t] = ((u64)(~fmap(sc)) << 32) | (u32)t;
    __syncthreads();

    for (int k = 2; k <= K_CAND; k <<= 1) {
        for (int j = k >> 1; j > 0; j >>= 1) {
            int ixj = t ^ j;
            if (ixj > t) {
                u64 a = keys[t], c = keys[ixj];
                bool up = ((t & k) == 0);
                if ((a > c) == up) { keys[t] = c; keys[ixj] = a; }
            }
            if (j >= 32) __syncthreads();
            else         __syncwarp();
        }
    }
    __syncthreads();

    if (t < K_OUT) {
        int slotw = (int)(keys[t] & 0xffffffffu);
        out[b * K_OUT + t] = (float)g_upids[b * K_CAND + slotw];
        if (out_size >= BATCH * K_OUT * 2)
            out[BATCH * K_OUT + b * K_OUT + t] = g_scores[b * K_CAND + slotw];
    }
}

// ---------------- launcher ----------------
extern "C" void kernel_launch(void* const* d_in, const int* in_sizes, int n_in,
                              void* d_out, int out_size) {
    int qi = 0, ii = 1, vi = 3;
    for (int i = 0; i < n_in; i++) {
        if (in_sizes[i] == BATCH * Q_LEN * HID)            qi = i;
        else if (in_sizes[i] == BATCH * K_CAND)            ii = i;
        else if (in_sizes[i] == N_PIDS * DOC_LEN * HID)    vi = i;
    }
    const float* q       = (const float*)d_in[qi];
    const void*  idx     = d_in[ii];
    const float* vectors = (const float*)d_in[vi];

    prep_kernel<<<64, 256>>>(idx, q);

    dim3 grid(BATCH, K_CAND);
    score_kernel<<<grid, 128>>>(vectors);

    topk_kernel<<<BATCH, K_CAND>>>((float*)d_out, out_size);
}

// round 16
// speedup vs baseline: 1.1517x; 1.0003x over previous
#include <cuda_runtime.h>
#include <cuda_fp16.h>
#include <math_constants.h>

// ---------------- problem constants ----------------
#define BATCH   32
#define Q_LEN   32
#define HID     128
#define DOC_LEN 128
#define K_CAND  256
#define K_OUT   16
#define N_PIDS  20000
#define N_EMB   (N_PIDS * DOC_LEN)

typedef unsigned long long u64;
typedef unsigned int u32;

// ---------------- device scratch ----------------
__device__ int    g_upids[BATCH * K_CAND];
__device__ int    g_ucnt[BATCH];
__device__ float  g_scores[BATCH * K_CAND];
// q pre-split fp16 B fragments: [b][s=8][t=4][lane=32] -> uint2 (b0,b1), hi & lo
__device__ uint2  g_qfh[BATCH * 8 * 4 * 32];
__device__ uint2  g_qfl[BATCH * 8 * 4 * 32];

// ---------------- helpers ----------------
__device__ __forceinline__ void split_h2(float2 v, u32& hi, u32& lo) {
    __half2 h = __float22half2_rn(v);
    float2 hf = __half22float2(h);
    __half2 l = __float22half2_rn(make_float2(v.x - hf.x, v.y - hf.y));
    hi = *reinterpret_cast<u32*>(&h);
    lo = *reinterpret_cast<u32*>(&l);
}
__device__ __forceinline__ void mma16(float* c, const u32* a, const u32* b) {
    asm volatile(
        "mma.sync.aligned.m16n8k16.row.col.f32.f16.f16.f32 "
        "{%0,%1,%2,%3}, {%4,%5,%6,%7}, {%8,%9}, {%0,%1,%2,%3};"
        : "+f"(c[0]), "+f"(c[1]), "+f"(c[2]), "+f"(c[3])
        : "r"(a[0]), "r"(a[1]), "r"(a[2]), "r"(a[3]), "r"(b[0]), "r"(b[1]));
}
// monotone map: ascending u32 <=> ascending float (works for -inf)
__device__ __forceinline__ u32 fmap(float f) {
    u32 s = __float_as_uint(f);
    return (s & 0x80000000u) ? ~s : (s | 0x80000000u);
}

// ---------------- kernel 1: prep (dedup for bid<32, qprep for bid>=32) -----
__global__ void prep_kernel(const void* idx_raw, const float* __restrict__ qv) {
    const int role = blockIdx.x >> 5;
    const int b    = blockIdx.x & 31;
    const int t    = threadIdx.x;

    if (role == 1) {
        const float* src = qv + (size_t)b * Q_LEN * HID;
        uint2* dh = g_qfh + (size_t)b * (8 * 4 * 32);
        uint2* dl = g_qfl + (size_t)b * (8 * 4 * 32);
        for (int idx = t; idx < 8 * 4 * 32; idx += 256) {
            int s  = idx >> 7;
            int tt = (idx >> 5) & 3;
            int l  = idx & 31;
            int n  = 8 * tt + (l >> 2);
            int k0 = 16 * s + 2 * (l & 3);
            u32 b0h, b0l, b1h, b1l;
            split_h2(make_float2(src[n * HID + k0],     src[n * HID + k0 + 1]), b0h, b0l);
            split_h2(make_float2(src[n * HID + k0 + 8], src[n * HID + k0 + 9]), b1h, b1l);
            dh[idx] = make_uint2(b0h, b1h);
            dl[idx] = make_uint2(b0l, b1l);
        }
        return;
    }

    // ---- dedup: sorted unique pids ----
    __shared__ int pids[K_CAND];
    __shared__ int wsum[8];
    __shared__ int s_ok;

    if (t == 0) s_ok = 1;
    __syncthreads();
    if (t < 128) {
        long long v = ((const long long*)idx_raw)[b * 128 + t];
        if (v < 0 || v >= (long long)N_EMB) atomicAnd(&s_ok, 0);
    }
    __syncthreads();
    const int is64 = s_ok;

    long long v;
    if (is64) v = ((const long long*)idx_raw)[b * K_CAND + t];
    else      v = (long long)(((const int*)idx_raw)[b * K_CAND + t]);
    pids[t] = (int)(v >> 7);   // emb2pid[i] == i / 128
    __syncthreads();

    for (int k = 2; k <= K_CAND; k <<= 1) {
        for (int j = k >> 1; j > 0; j >>= 1) {
            int ixj = t ^ j;
            if (ixj > t) {
                int a = pids[t], c = pids[ixj];
                bool up = ((t & k) == 0);
                if ((a > c) == up) { pids[t] = c; pids[ixj] = a; }
            }
            if (j >= 32) __syncthreads();
            else         __syncwarp();
        }
    }
    __syncthreads();

    int myv  = pids[t];
    int flag = (t == 0) || (myv != pids[t - 1]);
    unsigned mask = __ballot_sync(0xffffffffu, flag);
    int lane = t & 31, w = t >> 5;
    int pre  = __popc(mask & ((1u << lane) - 1));
    if (lane == 31) wsum[w] = pre + flag;
    __syncthreads();
    int base = 0;
    for (int i = 0; i < w; i++) base += wsum[i];
    int pos = base + pre;
    if (flag) g_upids[b * K_CAND + pos] = myv;
    if (t == K_CAND - 1) g_ucnt[b] = pos + flag;
}

// ---------------- kernel 2: direct-LDG 3xFP16 m16n8k16 scoring -------------
// Per-lane direct LDG.64 of MMA A-fragments (byte-perfect 32B sectors).
// Prefetch distance 2 with only 2 buffers: each step converts its buffer to
// hi/lo registers FIRST (freeing it), then issues step s+2's loads into it.
// 16 outstanding LDGs per warp -> covers DRAM latency at 16 warps/SM.
__global__ void __launch_bounds__(128, 4)
score_kernel(const float* __restrict__ vectors) {
    __shared__ float red[4 * 32];

    const int b    = blockIdx.x;
    const int slot = blockIdx.y;
    const int tid  = threadIdx.x;
    const int wid  = tid >> 5;
    const int lane = tid & 31;

    if (slot >= g_ucnt[b]) {
        if (tid == 0) g_scores[b * K_CAND + slot] = -CUDART_INF_F;
        return;
    }
    const int pid = g_upids[b * K_CAND + slot];
    const float* doc = vectors + (size_t)pid * DOC_LEN * HID;

    // per-lane fragment base: row group g = lane>>2, col pair c = lane&3
    const float* ap = doc + (size_t)(32 * wid + (lane >> 2)) * HID + 2 * (lane & 3);
    const uint2* qfh = g_qfh + (size_t)b * (8 * 4 * 32) + lane;
    const uint2* qfl = g_qfl + (size_t)b * (8 * 4 * 32) + lane;

    float acc[2][4][4];
#pragma unroll
    for (int mt = 0; mt < 2; mt++)
#pragma unroll
        for (int t = 0; t < 4; t++)
#pragma unroll
            for (int r = 0; r < 4; r++) acc[mt][t][r] = 0.0f;

    // fragment buffers: [buffer parity][mt][frag 0..3] float2
    float2 fr[2][2][4];

    // preload steps 0 and 1 (16 outstanding LDGs before any compute)
#pragma unroll
    for (int p = 0; p < 2; p++) {
#pragma unroll
        for (int mt = 0; mt < 2; mt++) {
            const float* q = ap + mt * 16 * HID + 16 * p;
            fr[p][mt][0] = __ldg((const float2*)(q));
            fr[p][mt][1] = __ldg((const float2*)(q + 8 * HID));
            fr[p][mt][2] = __ldg((const float2*)(q + 8));
            fr[p][mt][3] = __ldg((const float2*)(q + 8 * HID + 8));
        }
    }

#pragma unroll
    for (int s = 0; s < 8; s++) {
        const int cur = s & 1;

        // 1) convert current buffer to fp16 hi/lo (frees fr[cur])
        u32 ahi[2][4], alo[2][4];
#pragma unroll
        for (int mt = 0; mt < 2; mt++)
#pragma unroll
            for (int r = 0; r < 4; r++)
                split_h2(fr[cur][mt][r], ahi[mt][r], alo[mt][r]);

        // 2) prefetch step s+2 into the freed buffer (distance-2 pipeline)
        if (s < 6) {
#pragma unroll
            for (int mt = 0; mt < 2; mt++) {
                const float* p = ap + mt * 16 * HID + 16 * (s + 2);
                fr[cur][mt][0] = __ldg((const float2*)(p));
                fr[cur][mt][1] = __ldg((const float2*)(p + 8 * HID));
                fr[cur][mt][2] = __ldg((const float2*)(p + 8));
                fr[cur][mt][3] = __ldg((const float2*)(p + 8 * HID + 8));
            }
        }

        // 3) q fragments for this step (L1/L2-hot)
        uint2 qh[4], ql[4];
#pragma unroll
        for (int t = 0; t < 4; t++) {
            qh[t] = __ldg(&qfh[(s * 4 + t) * 32]);
            ql[t] = __ldg(&qfl[(s * 4 + t) * 32]);
        }

        // 4) 3-term MMA
#pragma unroll
        for (int t = 0; t < 4; t++) {
            u32 bh[2] = { qh[t].x, qh[t].y };
            u32 bl[2] = { ql[t].x, ql[t].y };
#pragma unroll
            for (int mt = 0; mt < 2; mt++) {
                mma16(acc[mt][t], ahi[mt], bh);   // hi*hi
                mma16(acc[mt][t], ahi[mt], bl);   // hi*lo
                mma16(acc[mt][t], alo[mt], bh);   // lo*hi
            }
        }
    }

    // epilogue: per-q max over this warp's 32 docs
    // C frag: c0(row g, col 2c), c1(+1), c2(row g+8, col 2c), c3(+1)
#pragma unroll
    for (int t = 0; t < 4; t++) {
        float mx0 = fmaxf(acc[0][t][0], acc[0][t][2]);
        mx0 = fmaxf(mx0, fmaxf(acc[1][t][0], acc[1][t][2]));
        float mx1 = fmaxf(acc[0][t][1], acc[0][t][3]);
        mx1 = fmaxf(mx1, fmaxf(acc[1][t][1], acc[1][t][3]));
#pragma unroll
        for (int o = 4; o <= 16; o <<= 1) {
            mx0 = fmaxf(mx0, __shfl_xor_sync(0xffffffffu, mx0, o));
            mx1 = fmaxf(mx1, __shfl_xor_sync(0xffffffffu, mx1, o));
        }
        if (lane < 4) {
            red[wid * 32 + 8 * t + 2 * lane + 0] = mx0;
            red[wid * 32 + 8 * t + 2 * lane + 1] = mx1;
        }
    }
    __syncthreads();

    if (wid == 0) {
        float m = fmaxf(fmaxf(red[lane], red[32 + lane]),
                        fmaxf(red[64 + lane], red[96 + lane]));
#pragma unroll
        for (int o = 16; o > 0; o >>= 1)
            m += __shfl_xor_sync(0xffffffffu, m, o);
        if (lane == 0)
            g_scores[b * K_CAND + slot] = m * (1.0f / (float)Q_LEN);
    }
}

// ---------------- kernel 3: bitonic-sort top-16 ----------------------------
__global__ void topk_kernel(float* __restrict__ out, int out_size) {
    const int b = blockIdx.x;
    const int t = threadIdx.x;    // 256
    __shared__ u64 keys[K_CAND];

    float sc = g_scores[b * K_CAND + t];
    keys[t] = ((u64)(~fmap(sc)) << 32) | (u32)t;
    __syncthreads();

    for (int k = 2; k <= K_CAND; k <<= 1) {
        for (int j = k >> 1; j > 0; j >>= 1) {
            int ixj = t ^ j;
            if (ixj > t) {
                u64 a = keys[t], c = keys[ixj];
                bool up = ((t & k) == 0);
                if ((a > c) == up) { keys[t] = c; keys[ixj] = a; }
            }
            if (j >= 32) __syncthreads();
            else         __syncwarp();
        }
    }
    __syncthreads();

    if (t < K_OUT) {
        int slotw = (int)(keys[t] & 0xffffffffu);
        out[b * K_OUT + t] = (float)g_upids[b * K_CAND + slotw];
        if (out_size >= BATCH * K_OUT * 2)
            out[BATCH * K_OUT + b * K_OUT + t] = g_scores[b * K_CAND + slotw];
    }
}

// ---------------- launcher ----------------
extern "C" void kernel_launch(void* const* d_in, const int* in_sizes, int n_in,
                              void* d_out, int out_size) {
    int qi = 0, ii = 1, vi = 3;
    for (int i = 0; i < n_in; i++) {
        if (in_sizes[i] == BATCH * Q_LEN * HID)            qi = i;
        else if (in_sizes[i] == BATCH * K_CAND)            ii = i;
        else if (in_sizes[i] == N_PIDS * DOC_LEN * HID)    vi = i;
    }
    const float* q       = (const float*)d_in[qi];
    const void*  idx     = d_in[ii];
    const float* vectors = (const float*)d_in[vi];

    prep_kernel<<<64, 256>>>(idx, q);

    dim3 grid(BATCH, K_CAND);
    score_kernel<<<grid, 128>>>(vectors);

    topk_kernel<<<BATCH, K_CAND>>>((float*)d_out, out_size);
}